// round 12
// baseline (speedup 1.0000x reference)
#include <cuda_runtime.h>
#include <cuda_fp16.h>
#include <cstdint>

// Problem constants
#define N_TOK 262144
#define DIM   64
#define KCB   512
#define GAMMA 0.99f

#define TPB     256
#define TOK_CTA 256
#define NCTA    (N_TOK / TOK_CTA)

// smem layout (bytes)
#define SM_B     0                     // 512x64 fp16 SW128 = 64KB
#define SM_BIAS  65536                 // 512 f32
#define SM_MAGIC 67584                 // 512 f32
#define SMEM_BYTES 69632

#define SW(o) ((o) ^ (((o) >> 3) & 0x70))

// device globals (zero-init at load; self-rezeroing each call)
__device__ float g_cs[KCB * DIM];
__device__ float g_cn[KCB];
__device__ unsigned int g_done;
__device__ uint4 g_bh[4096];           // fp16 codebook image (16B chunks)
__device__ float g_bias[KCB];
__device__ float g_magic[KCB];

// ---------------- helpers ----------------
__device__ __forceinline__ uint32_t smem_u32(const void* p) {
    uint32_t a;
    asm("{ .reg .u64 t; cvta.to.shared.u64 t, %1; cvt.u32.u64 %0, t; }" : "=r"(a) : "l"(p));
    return a;
}
__device__ __forceinline__ uint32_t h2rn(float a, float b) {
    __half2 h = __floats2half2_rn(a, b);
    return *reinterpret_cast<uint32_t*>(&h);
}
__device__ __forceinline__ float2 h2back(uint32_t u) {
    return __half22float2(*reinterpret_cast<__half2*>(&u));
}
__device__ __forceinline__ void red4(float* dst, float4 v) {
    asm volatile("red.global.add.v4.f32 [%0], {%1,%2,%3,%4};"
                 :: "l"(dst), "f"(v.x), "f"(v.y), "f"(v.z), "f"(v.w) : "memory");
}

#define LDMX4(R, A) \
    asm volatile("ldmatrix.sync.aligned.m8n8.x4.shared.b16 {%0,%1,%2,%3}, [%4];" \
                 : "=r"((R)[0]), "=r"((R)[1]), "=r"((R)[2]), "=r"((R)[3]) : "r"(A))

#define MMA(C, A, B0, B1) \
    asm volatile("mma.sync.aligned.m16n8k16.row.col.f32.f16.f16.f32 " \
                 "{%0,%1,%2,%3}, {%4,%5,%6,%7}, {%8,%9}, {%0,%1,%2,%3};" \
                 : "+f"((C)[0]), "+f"((C)[1]), "+f"((C)[2]), "+f"((C)[3]) \
                 : "r"((A)[0]), "r"((A)[1]), "r"((A)[2]), "r"((A)[3]), "r"(B0), "r"(B1))

// packed (mantissa<<9 | 511-k) top-2, unsigned max/min
__device__ __forceinline__ void upd2(uint32_t p, uint32_t& B, uint32_t& S) {
    uint32_t hi = max(B, p), lo = min(B, p);
    B = hi;
    S = max(S, lo);
}
// f = 2^23 + 256*(s+256); bits*512 wraps exponent exactly -> (mant<<9)|inv
__device__ __forceinline__ uint32_t packsc(float Craw, float magic, uint32_t inv) {
    float f = fmaxf(fmaf(Craw, 256.f, magic), 8388608.f);
    return __float_as_uint(f) * 512u + inv;
}

// ---------------- init: codebook -> fp16 image + bias + magic ----------------
__global__ void init_kernel(const float* __restrict__ vq) {
    const int i = blockIdx.x * blockDim.x + threadIdx.x;   // 0..4095
    const float4* p = reinterpret_cast<const float4*>(vq + (i >> 3) * DIM + (i & 7) * 8);
    float4 v0 = __ldg(p), v1 = __ldg(p + 1);
    uint4 h4;
    h4.x = h2rn(v0.x, v0.y); h4.y = h2rn(v0.z, v0.w);
    h4.z = h2rn(v1.x, v1.y); h4.w = h2rn(v1.z, v1.w);
    g_bh[i] = h4;
    float bb = v0.x * v0.x + v0.y * v0.y + v0.z * v0.z + v0.w * v0.w
             + v1.x * v1.x + v1.y * v1.y + v1.z * v1.z + v1.w * v1.w;
    #pragma unroll
    for (int o = 1; o < 8; o <<= 1) bb += __shfl_xor_sync(0xffffffffu, bb, o);
    if ((i & 7) == 0) {
        float bias = 0.5f * bb;
        g_bias[i >> 3]  = bias;
        g_magic[i >> 3] = 8388608.f + 256.f * (256.f - bias);
    }
}

// ---------------- fused main kernel ----------------
__global__ void __launch_bounds__(TPB, 3) vq_kernel(
    const float* __restrict__ x,
    const float* __restrict__ vq,
    const float* __restrict__ cs_in,
    const float* __restrict__ cn_in,
    float* __restrict__ q_out,
    float* __restrict__ vq_out,
    float* __restrict__ cs_out,
    float* __restrict__ cn_out)
{
    extern __shared__ __align__(1024) char smem[];
    float* sbias  = reinterpret_cast<float*>(smem + SM_BIAS);
    float* smagic = reinterpret_cast<float*>(smem + SM_MAGIC);
    const uint32_t sb = smem_u32(smem);
    const int tid = threadIdx.x;
    const int lane = tid & 31, wid = tid >> 5;
    const int g = lane >> 2, c = lane & 3;

    // ---- stage: plain copy from precomputed globals ----
    #pragma unroll
    for (int it = 0; it < 16; it++) {
        int i = tid + TPB * it;
        *reinterpret_cast<uint4*>(smem + SM_B + SW((uint32_t)(i * 16))) = g_bh[i];
    }
    #pragma unroll
    for (int it = 0; it < 2; it++) {
        int k = tid + TPB * it;
        sbias[k]  = g_bias[k];
        smagic[k] = g_magic[k];
    }

    // ---- A fragments + per-slot hi/mid norms (exact, per token) ----
    uint32_t a_f[2][4][4];
    float nh2p[4] = {0.f, 0.f, 0.f, 0.f}, nm2p[4] = {0.f, 0.f, 0.f, 0.f};
    const int rowbase = blockIdx.x * TOK_CTA + wid * 32;
    #pragma unroll
    for (int m = 0; m < 2; m++) {
        #pragma unroll
        for (int kt = 0; kt < 4; kt++) {
            const float* p = x + (size_t)(rowbase + m * 16 + g) * DIM + kt * 16 + 2 * c;
            float2 f0 = *reinterpret_cast<const float2*>(p);
            float2 f1 = *reinterpret_cast<const float2*>(p + 8);
            float2 f2 = *reinterpret_cast<const float2*>(p + 8 * DIM);
            float2 f3 = *reinterpret_cast<const float2*>(p + 8 * DIM + 8);
            a_f[m][kt][0] = h2rn(f0.x, f0.y);
            a_f[m][kt][1] = h2rn(f2.x, f2.y);
            a_f[m][kt][2] = h2rn(f1.x, f1.y);
            a_f[m][kt][3] = h2rn(f3.x, f3.y);
            float2 h0 = h2back(a_f[m][kt][0]), h1 = h2back(a_f[m][kt][1]);
            float2 h2 = h2back(a_f[m][kt][2]), h3 = h2back(a_f[m][kt][3]);
            nh2p[2 * m]     += h0.x * h0.x + h0.y * h0.y + h2.x * h2.x + h2.y * h2.y;
            nh2p[2 * m + 1] += h1.x * h1.x + h1.y * h1.y + h3.x * h3.x + h3.y * h3.y;
            float a0 = f0.x - h0.x, a1 = f0.y - h0.y, a2 = f1.x - h2.x, a3 = f1.y - h2.y;
            float b0 = f2.x - h1.x, b1 = f2.y - h1.y, b2 = f3.x - h3.x, b3 = f3.y - h3.y;
            nm2p[2 * m]     += a0 * a0 + a1 * a1 + a2 * a2 + a3 * a3;
            nm2p[2 * m + 1] += b0 * b0 + b1 * b1 + b2 * b2 + b3 * b3;
        }
    }
    #pragma unroll
    for (int o = 1; o <= 2; o <<= 1) {
        #pragma unroll
        for (int s = 0; s < 4; s++) {
            nh2p[s] += __shfl_xor_sync(0xffffffffu, nh2p[s], o);
            nm2p[s] += __shfl_xor_sync(0xffffffffu, nm2p[s], o);
        }
    }
    __syncthreads();

    // vmax (exact); vmidmax analytic: ||v_mid|| <= 2^-11 ||v|| + subnormal slack
    float vmax;
    {
        float vm = 0.f;
        #pragma unroll
        for (int j = 0; j < KCB / 32; j++) vm = fmaxf(vm, sbias[lane + 32 * j]);
        #pragma unroll
        for (int o = 16; o; o >>= 1) vm = fmaxf(vm, __shfl_xor_sync(0xffffffffu, vm, o));
        vmax = sqrtf(2.f * vm);
    }
    const float vmidmax = 4.8828125e-4f * vmax + 2e-6f;

    uint32_t Bp[4] = {0u, 0u, 0u, 0u}, Sp[4] = {0u, 0u, 0u, 0u};

    // ---- coarse: 64 blocks of 8 codewords; preload both B-frag halves ----
    #pragma unroll 1
    for (int nb = 0; nb < 64; nb++) {
        const int n0 = nb * 8;
        const uint32_t rowoff = (uint32_t)((n0 + (lane & 7)) * 128) + ((lane >> 3) * 16);
        uint32_t b0[4], b1[4];
        LDMX4(b0, sb + SM_B + SW(rowoff));
        LDMX4(b1, sb + SM_B + SW(rowoff + 64));
        float C[2][4] = {};
        MMA(C[0], a_f[0][0], b0[0], b0[1]);
        MMA(C[1], a_f[1][0], b0[0], b0[1]);
        MMA(C[0], a_f[0][1], b0[2], b0[3]);
        MMA(C[1], a_f[1][1], b0[2], b0[3]);
        MMA(C[0], a_f[0][2], b1[0], b1[1]);
        MMA(C[1], a_f[1][2], b1[0], b1[1]);
        MMA(C[0], a_f[0][3], b1[2], b1[3]);
        MMA(C[1], a_f[1][3], b1[2], b1[3]);
        const int kA = n0 + 2 * c;
        float2 mg = *reinterpret_cast<const float2*>(&smagic[kA]);
        const uint32_t inv0 = 511u - (uint32_t)kA, inv1 = 510u - (uint32_t)kA;
        upd2(packsc(C[0][0], mg.x, inv0), Bp[0], Sp[0]);
        upd2(packsc(C[0][1], mg.y, inv1), Bp[0], Sp[0]);
        upd2(packsc(C[0][2], mg.x, inv0), Bp[1], Sp[1]);
        upd2(packsc(C[0][3], mg.y, inv1), Bp[1], Sp[1]);
        upd2(packsc(C[1][0], mg.x, inv0), Bp[2], Sp[2]);
        upd2(packsc(C[1][1], mg.y, inv1), Bp[2], Sp[2]);
        upd2(packsc(C[1][2], mg.x, inv0), Bp[3], Sp[3]);
        upd2(packsc(C[1][3], mg.y, inv1), Bp[3], Sp[3]);
    }

    // ---- quad merge of packed top-2 ----
    #pragma unroll
    for (int mask = 1; mask <= 2; mask <<= 1) {
        #pragma unroll
        for (int s = 0; s < 4; s++) {
            uint32_t ob = __shfl_xor_sync(0xffffffffu, Bp[s], mask);
            uint32_t os = __shfl_xor_sync(0xffffffffu, Sp[s], mask);
            uint32_t lo = min(Bp[s], ob);
            Bp[s] = max(Bp[s], ob);
            Sp[s] = max(max(Sp[s], os), lo);
        }
    }
    // redistribute: lane L takes slot L>>3 from lane (L&7)*4
    uint32_t myB = 0u, myS = 0u;
    float myNh2 = 0.f, myNm2 = 0.f;
    #pragma unroll
    for (int s = 0; s < 4; s++) {
        const int srcl = (lane & 7) * 4;
        uint32_t vb = __shfl_sync(0xffffffffu, Bp[s], srcl);
        uint32_t vs = __shfl_sync(0xffffffffu, Sp[s], srcl);
        float nh = __shfl_sync(0xffffffffu, nh2p[s], srcl);
        float nm = __shfl_sync(0xffffffffu, nm2p[s], srcl);
        if ((lane >> 3) == s) { myB = vb; myS = vs; myNh2 = nh; myNm2 = nm; }
    }

    // ---- tiered decision (1 int unit = 1/256 score) ----
    const int tok = blockIdx.x * TOK_CTA + tid;
    const uint32_t I1 = myB >> 9, I2 = myS >> 9;
    int best_k = 511 - (int)(myB & 511u);
    const float nh = sqrtf(myNh2), nm = sqrtf(myNm2);
    const float marg = nm * vmax + nh * (vmidmax + 4e-6f * vmax) + 1e-6f;
    const int ithr = (int)(256.f * marg) + 3;
    bool fullf = (I1 < 512u) || (I1 >= 8388000u);

    // tier 2: exact fp32 pair rescore of {k1, k2}
    if (!fullf && (int)(I1 - I2) <= ithr) {
        const int k1 = best_k, k2 = 511 - (int)(myS & 511u);
        const float4* xp = reinterpret_cast<const float4*>(x + (size_t)tok * DIM);
        const float4* va = reinterpret_cast<const float4*>(vq + (size_t)k1 * DIM);
        const float4* vb = reinterpret_cast<const float4*>(vq + (size_t)k2 * DIM);
        float e1 = 0.f, e2 = 0.f;
        #pragma unroll
        for (int i = 0; i < 16; i++) {
            float4 xv = __ldg(xp + i), u = __ldg(va + i), w = __ldg(vb + i);
            e1 = fmaf(xv.x, u.x, fmaf(xv.y, u.y, fmaf(xv.z, u.z, fmaf(xv.w, u.w, e1))));
            e2 = fmaf(xv.x, w.x, fmaf(xv.y, w.y, fmaf(xv.z, w.z, fmaf(xv.w, w.w, e2))));
        }
        e1 -= sbias[k1];
        e2 -= sbias[k2];
        const float s2f = (float)I2 * 0.00390625f - 256.f;
        const float emax = fmaxf(e1, e2);
        const int km = (e2 > e1) ? k2 : ((e1 > e2) ? k1 : min(k1, k2));
        if (emax >= s2f + marg + 0.005f) best_k = km;
        else fullf = true;
    }

    // tier 3: cooperative exact full rescan (rare)
    {
        unsigned rm = __ballot_sync(0xffffffffu, fullf);
        const int sub = lane & 3;
        const int grp = lane >> 2;
        while (rm) {
            const int src = __ffs(rm) - 1;
            rm &= rm - 1;
            const int stok = blockIdx.x * TOK_CTA + wid * 32 + src;
            const float4* xp = reinterpret_cast<const float4*>(x + (size_t)stok * DIM) + sub * 4;
            float4 x0 = __ldg(xp), x1 = __ldg(xp + 1), x2 = __ldg(xp + 2), x3 = __ldg(xp + 3);
            float be = -3.4e38f;
            int bkk = 0;
            #pragma unroll 1
            for (int i = 0; i < 64; i++) {
                const int r = i * 8 + grp;
                const float4* vr = reinterpret_cast<const float4*>(vq + (size_t)r * DIM) + sub * 4;
                float4 v0 = __ldg(vr), v1 = __ldg(vr + 1), v2 = __ldg(vr + 2), v3 = __ldg(vr + 3);
                float d = x0.x * v0.x;
                d = fmaf(x0.y, v0.y, d); d = fmaf(x0.z, v0.z, d); d = fmaf(x0.w, v0.w, d);
                d = fmaf(x1.x, v1.x, d); d = fmaf(x1.y, v1.y, d); d = fmaf(x1.z, v1.z, d); d = fmaf(x1.w, v1.w, d);
                d = fmaf(x2.x, v2.x, d); d = fmaf(x2.y, v2.y, d); d = fmaf(x2.z, v2.z, d); d = fmaf(x2.w, v2.w, d);
                d = fmaf(x3.x, v3.x, d); d = fmaf(x3.y, v3.y, d); d = fmaf(x3.z, v3.z, d); d = fmaf(x3.w, v3.w, d);
                d += __shfl_xor_sync(0xffffffffu, d, 1);
                d += __shfl_xor_sync(0xffffffffu, d, 2);
                d -= sbias[r];
                if (d > be) { be = d; bkk = r; }
            }
            #pragma unroll
            for (int o = 4; o < 32; o <<= 1) {
                float ob = __shfl_xor_sync(0xffffffffu, be, o);
                int   ok = __shfl_xor_sync(0xffffffffu, bkk, o);
                if (ob > be || (ob == be && ok < bkk)) { be = ob; bkk = ok; }
            }
            if (lane == src) best_k = bkk;
        }
    }

    // ---- cooperative epilogue, batched (MLP 8): gather + vector-RED ----
    {
        const int cc = lane & 15;
        const int half = lane >> 4;
        #pragma unroll
        for (int p4 = 0; p4 < 4; p4++) {
            int kkv[4], gtv[4];
            float4 vv[4], xv[4];
            #pragma unroll
            for (int u = 0; u < 4; u++) {
                const int j = (p4 * 4 + u) * 2 + half;
                kkv[u] = __shfl_sync(0xffffffffu, best_k, j);
                gtv[u] = blockIdx.x * TOK_CTA + wid * 32 + j;
                vv[u] = __ldg(reinterpret_cast<const float4*>(vq + (size_t)kkv[u] * DIM) + cc);
                xv[u] = __ldg(reinterpret_cast<const float4*>(x + (size_t)gtv[u] * DIM) + cc);
            }
            #pragma unroll
            for (int u = 0; u < 4; u++) {
                reinterpret_cast<float4*>(q_out + (size_t)gtv[u] * DIM)[cc] = vv[u];
                red4(g_cs + (size_t)kkv[u] * DIM + cc * 4, xv[u]);
                if (cc == 0) atomicAdd(&g_cn[kkv[u]], 1.0f);
            }
        }
    }

    // ---- last CTA performs the EMA finalize ----
    __threadfence();
    __syncthreads();
    __shared__ int s_last;
    if (tid == 0) s_last = (atomicAdd(&g_done, 1u) == (unsigned)(gridDim.x - 1));
    __syncthreads();
    if (!s_last) return;
    __threadfence();

    float* scn = reinterpret_cast<float*>(smem);
    for (int k = tid; k < KCB; k += TPB) {
        float cn_acc = g_cn[k];
        g_cn[k] = 0.f;
        float cn_new = cn_in[k] * GAMMA + cn_acc * (1.0f - GAMMA);
        cn_out[k] = cn_new;
        scn[k] = cn_new;
    }
    __syncthreads();
    for (int idx = tid; idx < KCB * DIM; idx += TPB) {
        float cs_acc = g_cs[idx];
        g_cs[idx] = 0.f;
        float cs_new = cs_in[idx] * GAMMA + cs_acc * (1.0f - GAMMA);
        cs_out[idx] = cs_new;
        vq_out[idx] = cs_new / scn[idx >> 6];
    }
    if (tid == 0) g_done = 0u;
}

extern "C" void kernel_launch(void* const* d_in, const int* in_sizes, int n_in,
                              void* d_out, int out_size) {
    const float* x  = (const float*)d_in[0];   // [N, 64]
    const float* vq = (const float*)d_in[1];   // [512, 64]
    const float* cs = (const float*)d_in[2];   // [512, 64]
    const float* cn = (const float*)d_in[3];   // [512]

    float* out    = (float*)d_out;
    float* q_out  = out;                        // [N, 64]
    float* vq_out = out + (size_t)N_TOK * DIM;  // [512, 64]
    float* cs_out = vq_out + (size_t)KCB * DIM; // [512, 64]
    float* cn_out = cs_out + (size_t)KCB * DIM; // [512]

    cudaFuncSetAttribute(vq_kernel, cudaFuncAttributeMaxDynamicSharedMemorySize, SMEM_BYTES);
    init_kernel<<<16, 256>>>(vq);
    vq_kernel<<<NCTA, TPB, SMEM_BYTES>>>(x, vq, cs, cn, q_out, vq_out, cs_out, cn_out);
}

// round 13
// speedup vs baseline: 1.0889x; 1.0889x over previous
#include <cuda_runtime.h>
#include <cuda_fp16.h>
#include <cstdint>

// Problem constants
#define N_TOK 262144
#define DIM   64
#define KCB   512
#define GAMMA 0.99f

#define TPB     256
#define TOK_CTA 256
#define NCTA    (N_TOK / TOK_CTA)

// smem layout (bytes)
#define SM_B     0                     // 512x64 fp16 SW128 = 64KB
#define SM_BIAS  65536                 // 512 f32
#define SM_MAGIC 67584                 // 512 f32
#define SMEM_BYTES 69632

#define SW(o) ((o) ^ (((o) >> 3) & 0x70))

// device globals (zero-init at load; self-rezeroing / idempotent each call)
__device__ float g_cs[KCB * DIM];
__device__ float g_cn[KCB];
__device__ unsigned int g_done;
__device__ uint4 g_bh[4096];           // fp16 codebook image (16B chunks)
__device__ float g_bias[KCB];
__device__ float g_magic[KCB];
__device__ unsigned int g_vn2_b;       // bits of max ||v||^2   (atomicMax, idempotent)
__device__ unsigned int g_vm2_b;       // bits of max ||v_mid||^2

// ---------------- helpers ----------------
__device__ __forceinline__ uint32_t smem_u32(const void* p) {
    uint32_t a;
    asm("{ .reg .u64 t; cvta.to.shared.u64 t, %1; cvt.u32.u64 %0, t; }" : "=r"(a) : "l"(p));
    return a;
}
__device__ __forceinline__ uint32_t h2rn(float a, float b) {
    __half2 h = __floats2half2_rn(a, b);
    return *reinterpret_cast<uint32_t*>(&h);
}
__device__ __forceinline__ float2 h2back(uint32_t u) {
    return __half22float2(*reinterpret_cast<__half2*>(&u));
}
__device__ __forceinline__ void red4(float* dst, float4 v) {
    asm volatile("red.global.add.v4.f32 [%0], {%1,%2,%3,%4};"
                 :: "l"(dst), "f"(v.x), "f"(v.y), "f"(v.z), "f"(v.w) : "memory");
}

#define LDMX4(R, A) \
    asm volatile("ldmatrix.sync.aligned.m8n8.x4.shared.b16 {%0,%1,%2,%3}, [%4];" \
                 : "=r"((R)[0]), "=r"((R)[1]), "=r"((R)[2]), "=r"((R)[3]) : "r"(A))

#define MMA(C, A, B0, B1) \
    asm volatile("mma.sync.aligned.m16n8k16.row.col.f32.f16.f16.f32 " \
                 "{%0,%1,%2,%3}, {%4,%5,%6,%7}, {%8,%9}, {%0,%1,%2,%3};" \
                 : "+f"((C)[0]), "+f"((C)[1]), "+f"((C)[2]), "+f"((C)[3]) \
                 : "r"((A)[0]), "r"((A)[1]), "r"((A)[2]), "r"((A)[3]), "r"(B0), "r"(B1))

// packed (mantissa<<9 | 511-k) top-2, unsigned max/min
__device__ __forceinline__ void upd2(uint32_t p, uint32_t& B, uint32_t& S) {
    uint32_t hi = max(B, p), lo = min(B, p);
    B = hi;
    S = max(S, lo);
}
// f = 2^23 + 256*(s+256); bits*512 wraps exponent exactly -> (mant<<9)|inv
__device__ __forceinline__ uint32_t packsc(float Craw, float magic, uint32_t inv) {
    float f = fmaxf(fmaf(Craw, 256.f, magic), 8388608.f);
    return __float_as_uint(f) * 512u + inv;
}

// ---------------- init: codebook -> fp16 image + bias/magic + exact maxima ----
__global__ void init_kernel(const float* __restrict__ vq) {
    const int i = blockIdx.x * blockDim.x + threadIdx.x;   // 0..4095
    const float4* p = reinterpret_cast<const float4*>(vq + (i >> 3) * DIM + (i & 7) * 8);
    float4 v0 = __ldg(p), v1 = __ldg(p + 1);
    uint4 h4;
    h4.x = h2rn(v0.x, v0.y); h4.y = h2rn(v0.z, v0.w);
    h4.z = h2rn(v1.x, v1.y); h4.w = h2rn(v1.z, v1.w);
    g_bh[i] = h4;
    float2 b0 = h2back(h4.x), b1 = h2back(h4.y), b2 = h2back(h4.z), b3 = h2back(h4.w);
    float bb = v0.x * v0.x + v0.y * v0.y + v0.z * v0.z + v0.w * v0.w
             + v1.x * v1.x + v1.y * v1.y + v1.z * v1.z + v1.w * v1.w;
    float m0 = v0.x - b0.x, m1 = v0.y - b0.y, m2 = v0.z - b1.x, m3 = v0.w - b1.y;
    float m4 = v1.x - b2.x, m5 = v1.y - b2.y, m6 = v1.z - b3.x, m7 = v1.w - b3.y;
    float nmw = m0 * m0 + m1 * m1 + m2 * m2 + m3 * m3
              + m4 * m4 + m5 * m5 + m6 * m6 + m7 * m7;
    #pragma unroll
    for (int o = 1; o < 8; o <<= 1) {
        bb  += __shfl_xor_sync(0xffffffffu, bb, o);
        nmw += __shfl_xor_sync(0xffffffffu, nmw, o);
    }
    if ((i & 7) == 0) {
        float bias = 0.5f * bb;
        g_bias[i >> 3]  = bias;
        g_magic[i >> 3] = 8388608.f + 256.f * (256.f - bias);
        // non-negative floats: uint compare == float compare; idempotent across replays
        atomicMax(&g_vn2_b, __float_as_uint(bb));
        atomicMax(&g_vm2_b, __float_as_uint(nmw));
    }
}

// ---------------- fused main kernel ----------------
__global__ void __launch_bounds__(TPB, 3) vq_kernel(
    const float* __restrict__ x,
    const float* __restrict__ vq,
    const float* __restrict__ cs_in,
    const float* __restrict__ cn_in,
    float* __restrict__ q_out,
    float* __restrict__ vq_out,
    float* __restrict__ cs_out,
    float* __restrict__ cn_out)
{
    extern __shared__ __align__(1024) char smem[];
    float* sbias  = reinterpret_cast<float*>(smem + SM_BIAS);
    float* smagic = reinterpret_cast<float*>(smem + SM_MAGIC);
    const uint32_t sb = smem_u32(smem);
    const int tid = threadIdx.x;
    const int lane = tid & 31, wid = tid >> 5;
    const int g = lane >> 2, c = lane & 3;

    // ---- stage: plain copy from precomputed globals ----
    #pragma unroll
    for (int it = 0; it < 16; it++) {
        int i = tid + TPB * it;
        *reinterpret_cast<uint4*>(smem + SM_B + SW((uint32_t)(i * 16))) = g_bh[i];
    }
    #pragma unroll
    for (int it = 0; it < 2; it++) {
        int k = tid + TPB * it;
        sbias[k]  = g_bias[k];
        smagic[k] = g_magic[k];
    }
    // exact codebook maxima (computed once in init)
    const float vmax    = sqrtf(__uint_as_float(*(volatile unsigned int*)&g_vn2_b));
    const float vmidmax = sqrtf(__uint_as_float(*(volatile unsigned int*)&g_vm2_b));

    // ---- A fragments + per-slot hi/mid norms (exact, per token) ----
    uint32_t a_f[2][4][4];
    float nh2p[4] = {0.f, 0.f, 0.f, 0.f}, nm2p[4] = {0.f, 0.f, 0.f, 0.f};
    const int rowbase = blockIdx.x * TOK_CTA + wid * 32;
    #pragma unroll
    for (int m = 0; m < 2; m++) {
        #pragma unroll
        for (int kt = 0; kt < 4; kt++) {
            const float* p = x + (size_t)(rowbase + m * 16 + g) * DIM + kt * 16 + 2 * c;
            float2 f0 = *reinterpret_cast<const float2*>(p);
            float2 f1 = *reinterpret_cast<const float2*>(p + 8);
            float2 f2 = *reinterpret_cast<const float2*>(p + 8 * DIM);
            float2 f3 = *reinterpret_cast<const float2*>(p + 8 * DIM + 8);
            a_f[m][kt][0] = h2rn(f0.x, f0.y);
            a_f[m][kt][1] = h2rn(f2.x, f2.y);
            a_f[m][kt][2] = h2rn(f1.x, f1.y);
            a_f[m][kt][3] = h2rn(f3.x, f3.y);
            float2 h0 = h2back(a_f[m][kt][0]), h1 = h2back(a_f[m][kt][1]);
            float2 h2 = h2back(a_f[m][kt][2]), h3 = h2back(a_f[m][kt][3]);
            nh2p[2 * m]     += h0.x * h0.x + h0.y * h0.y + h2.x * h2.x + h2.y * h2.y;
            nh2p[2 * m + 1] += h1.x * h1.x + h1.y * h1.y + h3.x * h3.x + h3.y * h3.y;
            float a0 = f0.x - h0.x, a1 = f0.y - h0.y, a2 = f1.x - h2.x, a3 = f1.y - h2.y;
            float b0 = f2.x - h1.x, b1 = f2.y - h1.y, b2 = f3.x - h3.x, b3 = f3.y - h3.y;
            nm2p[2 * m]     += a0 * a0 + a1 * a1 + a2 * a2 + a3 * a3;
            nm2p[2 * m + 1] += b0 * b0 + b1 * b1 + b2 * b2 + b3 * b3;
        }
    }
    #pragma unroll
    for (int o = 1; o <= 2; o <<= 1) {
        #pragma unroll
        for (int s = 0; s < 4; s++) {
            nh2p[s] += __shfl_xor_sync(0xffffffffu, nh2p[s], o);
            nm2p[s] += __shfl_xor_sync(0xffffffffu, nm2p[s], o);
        }
    }
    __syncthreads();

    uint32_t Bp[4] = {0u, 0u, 0u, 0u}, Sp[4] = {0u, 0u, 0u, 0u};

    // ---- coarse: 64 blocks of 8 codewords; preload both B-frag halves ----
    #pragma unroll 1
    for (int nb = 0; nb < 64; nb++) {
        const int n0 = nb * 8;
        const uint32_t rowoff = (uint32_t)((n0 + (lane & 7)) * 128) + ((lane >> 3) * 16);
        uint32_t b0[4], b1[4];
        LDMX4(b0, sb + SM_B + SW(rowoff));
        LDMX4(b1, sb + SM_B + SW(rowoff + 64));
        float C[2][4] = {};
        MMA(C[0], a_f[0][0], b0[0], b0[1]);
        MMA(C[1], a_f[1][0], b0[0], b0[1]);
        MMA(C[0], a_f[0][1], b0[2], b0[3]);
        MMA(C[1], a_f[1][1], b0[2], b0[3]);
        MMA(C[0], a_f[0][2], b1[0], b1[1]);
        MMA(C[1], a_f[1][2], b1[0], b1[1]);
        MMA(C[0], a_f[0][3], b1[2], b1[3]);
        MMA(C[1], a_f[1][3], b1[2], b1[3]);
        const int kA = n0 + 2 * c;
        float2 mg = *reinterpret_cast<const float2*>(&smagic[kA]);
        const uint32_t inv0 = 511u - (uint32_t)kA, inv1 = 510u - (uint32_t)kA;
        upd2(packsc(C[0][0], mg.x, inv0), Bp[0], Sp[0]);
        upd2(packsc(C[0][1], mg.y, inv1), Bp[0], Sp[0]);
        upd2(packsc(C[0][2], mg.x, inv0), Bp[1], Sp[1]);
        upd2(packsc(C[0][3], mg.y, inv1), Bp[1], Sp[1]);
        upd2(packsc(C[1][0], mg.x, inv0), Bp[2], Sp[2]);
        upd2(packsc(C[1][1], mg.y, inv1), Bp[2], Sp[2]);
        upd2(packsc(C[1][2], mg.x, inv0), Bp[3], Sp[3]);
        upd2(packsc(C[1][3], mg.y, inv1), Bp[3], Sp[3]);
    }

    // ---- quad merge of packed top-2 ----
    #pragma unroll
    for (int mask = 1; mask <= 2; mask <<= 1) {
        #pragma unroll
        for (int s = 0; s < 4; s++) {
            uint32_t ob = __shfl_xor_sync(0xffffffffu, Bp[s], mask);
            uint32_t os = __shfl_xor_sync(0xffffffffu, Sp[s], mask);
            uint32_t lo = min(Bp[s], ob);
            Bp[s] = max(Bp[s], ob);
            Sp[s] = max(max(Sp[s], os), lo);
        }
    }
    // redistribute: lane L takes slot L>>3 from lane (L&7)*4
    uint32_t myB = 0u, myS = 0u;
    float myNh2 = 0.f, myNm2 = 0.f;
    #pragma unroll
    for (int s = 0; s < 4; s++) {
        const int srcl = (lane & 7) * 4;
        uint32_t vb = __shfl_sync(0xffffffffu, Bp[s], srcl);
        uint32_t vs = __shfl_sync(0xffffffffu, Sp[s], srcl);
        float nh = __shfl_sync(0xffffffffu, nh2p[s], srcl);
        float nm = __shfl_sync(0xffffffffu, nm2p[s], srcl);
        if ((lane >> 3) == s) { myB = vb; myS = vs; myNh2 = nh; myNm2 = nm; }
    }

    // ---- tiered decision (1 int unit = 1/256 score) ----
    const int tok = blockIdx.x * TOK_CTA + tid;
    const uint32_t I1 = myB >> 9, I2 = myS >> 9;
    int best_k = 511 - (int)(myB & 511u);
    const float nh = sqrtf(myNh2), nm = sqrtf(myNm2);
    const float marg = nm * vmax + nh * (vmidmax + 4e-6f * vmax) + 1e-6f;
    const int ithr = (int)(256.f * marg) + 3;
    bool fullf = (I1 < 512u) || (I1 >= 8388000u);

    // tier 2: exact fp32 pair rescore of {k1, k2}
    if (!fullf && (int)(I1 - I2) <= ithr) {
        const int k1 = best_k, k2 = 511 - (int)(myS & 511u);
        const float4* xp = reinterpret_cast<const float4*>(x + (size_t)tok * DIM);
        const float4* va = reinterpret_cast<const float4*>(vq + (size_t)k1 * DIM);
        const float4* vb = reinterpret_cast<const float4*>(vq + (size_t)k2 * DIM);
        float e1 = 0.f, e2 = 0.f;
        #pragma unroll
        for (int i = 0; i < 16; i++) {
            float4 xv = __ldg(xp + i), u = __ldg(va + i), w = __ldg(vb + i);
            e1 = fmaf(xv.x, u.x, fmaf(xv.y, u.y, fmaf(xv.z, u.z, fmaf(xv.w, u.w, e1))));
            e2 = fmaf(xv.x, w.x, fmaf(xv.y, w.y, fmaf(xv.z, w.z, fmaf(xv.w, w.w, e2))));
        }
        e1 -= sbias[k1];
        e2 -= sbias[k2];
        const float s2f = (float)I2 * 0.00390625f - 256.f;
        const float emax = fmaxf(e1, e2);
        const int km = (e2 > e1) ? k2 : ((e1 > e2) ? k1 : min(k1, k2));
        if (emax >= s2f + marg + 0.005f) best_k = km;
        else fullf = true;
    }

    // tier 3: cooperative exact full rescan (rare)
    {
        unsigned rm = __ballot_sync(0xffffffffu, fullf);
        const int sub = lane & 3;
        const int grp = lane >> 2;
        while (rm) {
            const int src = __ffs(rm) - 1;
            rm &= rm - 1;
            const int stok = blockIdx.x * TOK_CTA + wid * 32 + src;
            const float4* xp = reinterpret_cast<const float4*>(x + (size_t)stok * DIM) + sub * 4;
            float4 x0 = __ldg(xp), x1 = __ldg(xp + 1), x2 = __ldg(xp + 2), x3 = __ldg(xp + 3);
            float be = -3.4e38f;
            int bkk = 0;
            #pragma unroll 1
            for (int i = 0; i < 64; i++) {
                const int r = i * 8 + grp;
                const float4* vr = reinterpret_cast<const float4*>(vq + (size_t)r * DIM) + sub * 4;
                float4 v0 = __ldg(vr), v1 = __ldg(vr + 1), v2 = __ldg(vr + 2), v3 = __ldg(vr + 3);
                float d = x0.x * v0.x;
                d = fmaf(x0.y, v0.y, d); d = fmaf(x0.z, v0.z, d); d = fmaf(x0.w, v0.w, d);
                d = fmaf(x1.x, v1.x, d); d = fmaf(x1.y, v1.y, d); d = fmaf(x1.z, v1.z, d); d = fmaf(x1.w, v1.w, d);
                d = fmaf(x2.x, v2.x, d); d = fmaf(x2.y, v2.y, d); d = fmaf(x2.z, v2.z, d); d = fmaf(x2.w, v2.w, d);
                d = fmaf(x3.x, v3.x, d); d = fmaf(x3.y, v3.y, d); d = fmaf(x3.z, v3.z, d); d = fmaf(x3.w, v3.w, d);
                d += __shfl_xor_sync(0xffffffffu, d, 1);
                d += __shfl_xor_sync(0xffffffffu, d, 2);
                d -= sbias[r];
                if (d > be) { be = d; bkk = r; }
            }
            #pragma unroll
            for (int o = 4; o < 32; o <<= 1) {
                float ob = __shfl_xor_sync(0xffffffffu, be, o);
                int   ok = __shfl_xor_sync(0xffffffffu, bkk, o);
                if (ob > be || (ob == be && ok < bkk)) { be = ob; bkk = ok; }
            }
            if (lane == src) best_k = bkk;
        }
    }

    // ---- cooperative epilogue, batched (MLP 8): gather + vector-RED ----
    {
        const int cc = lane & 15;
        const int half = lane >> 4;
        #pragma unroll
        for (int p4 = 0; p4 < 4; p4++) {
            int kkv[4], gtv[4];
            float4 vv[4], xv[4];
            #pragma unroll
            for (int u = 0; u < 4; u++) {
                const int j = (p4 * 4 + u) * 2 + half;
                kkv[u] = __shfl_sync(0xffffffffu, best_k, j);
                gtv[u] = blockIdx.x * TOK_CTA + wid * 32 + j;
                vv[u] = __ldg(reinterpret_cast<const float4*>(vq + (size_t)kkv[u] * DIM) + cc);
                xv[u] = __ldg(reinterpret_cast<const float4*>(x + (size_t)gtv[u] * DIM) + cc);
            }
            #pragma unroll
            for (int u = 0; u < 4; u++) {
                reinterpret_cast<float4*>(q_out + (size_t)gtv[u] * DIM)[cc] = vv[u];
                red4(g_cs + (size_t)kkv[u] * DIM + cc * 4, xv[u]);
                if (cc == 0) atomicAdd(&g_cn[kkv[u]], 1.0f);
            }
        }
    }

    // ---- last CTA performs the EMA finalize ----
    __threadfence();
    __syncthreads();
    __shared__ int s_last;
    if (tid == 0) s_last = (atomicAdd(&g_done, 1u) == (unsigned)(gridDim.x - 1));
    __syncthreads();
    if (!s_last) return;
    __threadfence();

    float* scn = reinterpret_cast<float*>(smem);
    for (int k = tid; k < KCB; k += TPB) {
        float cn_acc = g_cn[k];
        g_cn[k] = 0.f;
        float cn_new = cn_in[k] * GAMMA + cn_acc * (1.0f - GAMMA);
        cn_out[k] = cn_new;
        scn[k] = cn_new;
    }
    __syncthreads();
    for (int idx = tid; idx < KCB * DIM; idx += TPB) {
        float cs_acc = g_cs[idx];
        g_cs[idx] = 0.f;
        float cs_new = cs_in[idx] * GAMMA + cs_acc * (1.0f - GAMMA);
        cs_out[idx] = cs_new;
        vq_out[idx] = cs_new / scn[idx >> 6];
    }
    if (tid == 0) g_done = 0u;
}

extern "C" void kernel_launch(void* const* d_in, const int* in_sizes, int n_in,
                              void* d_out, int out_size) {
    const float* x  = (const float*)d_in[0];   // [N, 64]
    const float* vq = (const float*)d_in[1];   // [512, 64]
    const float* cs = (const float*)d_in[2];   // [512, 64]
    const float* cn = (const float*)d_in[3];   // [512]

    float* out    = (float*)d_out;
    float* q_out  = out;                        // [N, 64]
    float* vq_out = out + (size_t)N_TOK * DIM;  // [512, 64]
    float* cs_out = vq_out + (size_t)KCB * DIM; // [512, 64]
    float* cn_out = cs_out + (size_t)KCB * DIM; // [512]

    cudaFuncSetAttribute(vq_kernel, cudaFuncAttributeMaxDynamicSharedMemorySize, SMEM_BYTES);
    init_kernel<<<16, 256>>>(vq);
    vq_kernel<<<NCTA, TPB, SMEM_BYTES>>>(x, vq, cs, cn, q_out, vq_out, cs_out, cn_out);
}

// round 15
// speedup vs baseline: 1.1114x; 1.0207x over previous
#include <cuda_runtime.h>
#include <cuda_fp16.h>
#include <cstdint>

// Problem constants
#define N_TOK 262144
#define DIM   64
#define KCB   512
#define GAMMA 0.99f

#define TPB     256
#define TOK_CTA 256
#define NCTA    (N_TOK / TOK_CTA)

// smem layout (bytes)
#define SM_B     0                     // 512x64 fp16 SW128 = 64KB
#define SM_BIAS  65536                 // 512 f32
#define SM_MAGIC 67584                 // 512 f32
#define SM_MARG  69632                 // 256 f32 per-token margins
#define SMEM_BYTES 70656

#define SW(o) ((o) ^ (((o) >> 3) & 0x70))

// device globals (zero-init at load; self-rezeroing / idempotent each call)
__device__ float g_cs[KCB * DIM];
__device__ float g_cn[KCB];
__device__ unsigned int g_done;
__device__ uint4 g_bh[4096];           // fp16 codebook image (16B chunks)
__device__ float g_bias[KCB];
__device__ float g_magic[KCB];
__device__ unsigned int g_vn2_b;       // bits of max ||v||^2   (atomicMax, idempotent)
__device__ unsigned int g_vm2_b;       // bits of max ||v_mid||^2

// ---------------- helpers ----------------
__device__ __forceinline__ uint32_t smem_u32(const void* p) {
    uint32_t a;
    asm("{ .reg .u64 t; cvta.to.shared.u64 t, %1; cvt.u32.u64 %0, t; }" : "=r"(a) : "l"(p));
    return a;
}
__device__ __forceinline__ uint32_t h2rn(float a, float b) {
    __half2 h = __floats2half2_rn(a, b);
    return *reinterpret_cast<uint32_t*>(&h);
}
__device__ __forceinline__ float2 h2back(uint32_t u) {
    return __half22float2(*reinterpret_cast<__half2*>(&u));
}
__device__ __forceinline__ void red4(float* dst, float4 v) {
    asm volatile("red.global.add.v4.f32 [%0], {%1,%2,%3,%4};"
                 :: "l"(dst), "f"(v.x), "f"(v.y), "f"(v.z), "f"(v.w) : "memory");
}

#define LDMX4(R, A) \
    asm volatile("ldmatrix.sync.aligned.m8n8.x4.shared.b16 {%0,%1,%2,%3}, [%4];" \
                 : "=r"((R)[0]), "=r"((R)[1]), "=r"((R)[2]), "=r"((R)[3]) : "r"(A))

#define MMA(C, A, B0, B1) \
    asm volatile("mma.sync.aligned.m16n8k16.row.col.f32.f16.f16.f32 " \
                 "{%0,%1,%2,%3}, {%4,%5,%6,%7}, {%8,%9}, {%0,%1,%2,%3};" \
                 : "+f"((C)[0]), "+f"((C)[1]), "+f"((C)[2]), "+f"((C)[3]) \
                 : "r"((A)[0]), "r"((A)[1]), "r"((A)[2]), "r"((A)[3]), "r"(B0), "r"(B1))

// packed (mantissa<<9 | 511-k) top-2, unsigned max/min
__device__ __forceinline__ void upd2(uint32_t p, uint32_t& B, uint32_t& S) {
    uint32_t hi = max(B, p), lo = min(B, p);
    B = hi;
    S = max(S, lo);
}
// f = 2^23 + 256*(s+256); bits*512 wraps exponent exactly -> (mant<<9)|inv
__device__ __forceinline__ uint32_t packsc(float Craw, float magic, uint32_t inv) {
    float f = fmaxf(fmaf(Craw, 256.f, magic), 8388608.f);
    return __float_as_uint(f) * 512u + inv;
}

// ---------------- init: codebook -> fp16 image + bias/magic + exact maxima ----
__global__ void init_kernel(const float* __restrict__ vq) {
    const int i = blockIdx.x * blockDim.x + threadIdx.x;   // 0..4095
    const float4* p = reinterpret_cast<const float4*>(vq + (i >> 3) * DIM + (i & 7) * 8);
    float4 v0 = __ldg(p), v1 = __ldg(p + 1);
    uint4 h4;
    h4.x = h2rn(v0.x, v0.y); h4.y = h2rn(v0.z, v0.w);
    h4.z = h2rn(v1.x, v1.y); h4.w = h2rn(v1.z, v1.w);
    g_bh[i] = h4;
    float2 b0 = h2back(h4.x), b1 = h2back(h4.y), b2 = h2back(h4.z), b3 = h2back(h4.w);
    float bb = v0.x * v0.x + v0.y * v0.y + v0.z * v0.z + v0.w * v0.w
             + v1.x * v1.x + v1.y * v1.y + v1.z * v1.z + v1.w * v1.w;
    float m0 = v0.x - b0.x, m1 = v0.y - b0.y, m2 = v0.z - b1.x, m3 = v0.w - b1.y;
    float m4 = v1.x - b2.x, m5 = v1.y - b2.y, m6 = v1.z - b3.x, m7 = v1.w - b3.y;
    float nmw = m0 * m0 + m1 * m1 + m2 * m2 + m3 * m3
              + m4 * m4 + m5 * m5 + m6 * m6 + m7 * m7;
    #pragma unroll
    for (int o = 1; o < 8; o <<= 1) {
        bb  += __shfl_xor_sync(0xffffffffu, bb, o);
        nmw += __shfl_xor_sync(0xffffffffu, nmw, o);
    }
    if ((i & 7) == 0) {
        float bias = 0.5f * bb;
        g_bias[i >> 3]  = bias;
        g_magic[i >> 3] = 8388608.f + 256.f * (256.f - bias);
        atomicMax(&g_vn2_b, __float_as_uint(bb));
        atomicMax(&g_vm2_b, __float_as_uint(nmw));
    }
}

// ---------------- fused main kernel ----------------
__global__ void __launch_bounds__(TPB, 3) vq_kernel(
    const float* __restrict__ x,
    const float* __restrict__ vq,
    const float* __restrict__ cs_in,
    const float* __restrict__ cn_in,
    float* __restrict__ q_out,
    float* __restrict__ vq_out,
    float* __restrict__ cs_out,
    float* __restrict__ cn_out)
{
    extern __shared__ __align__(1024) char smem[];
    float* sbias  = reinterpret_cast<float*>(smem + SM_BIAS);
    float* smagic = reinterpret_cast<float*>(smem + SM_MAGIC);
    float* smarg  = reinterpret_cast<float*>(smem + SM_MARG);
    const uint32_t sb = smem_u32(smem);
    const int tid = threadIdx.x;
    const int lane = tid & 31, wid = tid >> 5;
    const int g = lane >> 2, c = lane & 3;

    // ---- stage: plain copy from precomputed globals ----
    #pragma unroll
    for (int it = 0; it < 16; it++) {
        int i = tid + TPB * it;
        *reinterpret_cast<uint4*>(smem + SM_B + SW((uint32_t)(i * 16))) = g_bh[i];
    }
    #pragma unroll
    for (int it = 0; it < 2; it++) {
        int k = tid + TPB * it;
        sbias[k]  = g_bias[k];
        smagic[k] = g_magic[k];
    }
    const float vmax    = sqrtf(__uint_as_float(*(volatile unsigned int*)&g_vn2_b));
    const float vmidmax = sqrtf(__uint_as_float(*(volatile unsigned int*)&g_vm2_b));

    // ---- A fragments + per-slot hi/mid norms (exact, per token) ----
    uint32_t a_f[2][4][4];
    {
        float nh2p[4] = {0.f, 0.f, 0.f, 0.f}, nm2p[4] = {0.f, 0.f, 0.f, 0.f};
        const int rowbase = blockIdx.x * TOK_CTA + wid * 32;
        #pragma unroll
        for (int m = 0; m < 2; m++) {
            #pragma unroll
            for (int kt = 0; kt < 4; kt++) {
                const float* p = x + (size_t)(rowbase + m * 16 + g) * DIM + kt * 16 + 2 * c;
                float2 f0 = *reinterpret_cast<const float2*>(p);
                float2 f1 = *reinterpret_cast<const float2*>(p + 8);
                float2 f2 = *reinterpret_cast<const float2*>(p + 8 * DIM);
                float2 f3 = *reinterpret_cast<const float2*>(p + 8 * DIM + 8);
                a_f[m][kt][0] = h2rn(f0.x, f0.y);
                a_f[m][kt][1] = h2rn(f2.x, f2.y);
                a_f[m][kt][2] = h2rn(f1.x, f1.y);
                a_f[m][kt][3] = h2rn(f3.x, f3.y);
                float2 h0 = h2back(a_f[m][kt][0]), h1 = h2back(a_f[m][kt][1]);
                float2 h2 = h2back(a_f[m][kt][2]), h3 = h2back(a_f[m][kt][3]);
                nh2p[2 * m]     += h0.x * h0.x + h0.y * h0.y + h2.x * h2.x + h2.y * h2.y;
                nh2p[2 * m + 1] += h1.x * h1.x + h1.y * h1.y + h3.x * h3.x + h3.y * h3.y;
                float a0 = f0.x - h0.x, a1 = f0.y - h0.y, a2 = f1.x - h2.x, a3 = f1.y - h2.y;
                float b0 = f2.x - h1.x, b1 = f2.y - h1.y, b2 = f3.x - h3.x, b3 = f3.y - h3.y;
                nm2p[2 * m]     += a0 * a0 + a1 * a1 + a2 * a2 + a3 * a3;
                nm2p[2 * m + 1] += b0 * b0 + b1 * b1 + b2 * b2 + b3 * b3;
            }
        }
        #pragma unroll
        for (int o = 1; o <= 2; o <<= 1) {
            #pragma unroll
            for (int s = 0; s < 4; s++) {
                nh2p[s] += __shfl_xor_sync(0xffffffffu, nh2p[s], o);
                nm2p[s] += __shfl_xor_sync(0xffffffffu, nm2p[s], o);
            }
        }
        // per-token margin -> smem (token-in-warp = 8s + g)
        if (c == 0) {
            #pragma unroll
            for (int s = 0; s < 4; s++) {
                float nhv = sqrtf(nh2p[s]), nmv = sqrtf(nm2p[s]);
                smarg[wid * 32 + 8 * s + g] =
                    nmv * vmax + nhv * (vmidmax + 4e-6f * vmax) + 1e-6f;
            }
        }
    }
    __syncthreads();

    uint32_t Bp[4] = {0u, 0u, 0u, 0u}, Sp[4] = {0u, 0u, 0u, 0u};

    // ---- coarse loop, software-pipelined via unroll 2 ----
    // SW(base + nb*1024) == SW(base) + nb*1024 (increment above swizzle bits)
    // SW(rowoff + 64)    == SW(rowoff) ^ 64    (bit 6 of rowoff clear; mask unchanged)
    const uint32_t adr0 = sb + SM_B +
        SW((uint32_t)((lane & 7) * 128) + (uint32_t)((lane >> 3) * 16));
    #pragma unroll 2
    for (int nb = 0; nb < 64; nb++) {
        const uint32_t a0 = adr0 + (uint32_t)nb * 1024u;
        uint32_t b0[4], b1[4];
        LDMX4(b0, a0);
        LDMX4(b1, a0 ^ 64u);
        float C[2][4] = {};
        MMA(C[0], a_f[0][0], b0[0], b0[1]);
        MMA(C[1], a_f[1][0], b0[0], b0[1]);
        MMA(C[0], a_f[0][1], b0[2], b0[3]);
        MMA(C[1], a_f[1][1], b0[2], b0[3]);
        MMA(C[0], a_f[0][2], b1[0], b1[1]);
        MMA(C[1], a_f[1][2], b1[0], b1[1]);
        MMA(C[0], a_f[0][3], b1[2], b1[3]);
        MMA(C[1], a_f[1][3], b1[2], b1[3]);
        const int kA = nb * 8 + 2 * c;
        float2 mg = *reinterpret_cast<const float2*>(&smagic[kA]);
        const uint32_t inv0 = 511u - (uint32_t)kA, inv1 = 510u - (uint32_t)kA;
        upd2(packsc(C[0][0], mg.x, inv0), Bp[0], Sp[0]);
        upd2(packsc(C[0][1], mg.y, inv1), Bp[0], Sp[0]);
        upd2(packsc(C[0][2], mg.x, inv0), Bp[1], Sp[1]);
        upd2(packsc(C[0][3], mg.y, inv1), Bp[1], Sp[1]);
        upd2(packsc(C[1][0], mg.x, inv0), Bp[2], Sp[2]);
        upd2(packsc(C[1][1], mg.y, inv1), Bp[2], Sp[2]);
        upd2(packsc(C[1][2], mg.x, inv0), Bp[3], Sp[3]);
        upd2(packsc(C[1][3], mg.y, inv1), Bp[3], Sp[3]);
    }

    // ---- quad merge of packed top-2 ----
    #pragma unroll
    for (int mask = 1; mask <= 2; mask <<= 1) {
        #pragma unroll
        for (int s = 0; s < 4; s++) {
            uint32_t ob = __shfl_xor_sync(0xffffffffu, Bp[s], mask);
            uint32_t os = __shfl_xor_sync(0xffffffffu, Sp[s], mask);
            uint32_t lo = min(Bp[s], ob);
            Bp[s] = max(Bp[s], ob);
            Sp[s] = max(max(Sp[s], os), lo);
        }
    }
    // redistribute: lane L takes slot L>>3 from lane (L&7)*4
    uint32_t myB = 0u, myS = 0u;
    #pragma unroll
    for (int s = 0; s < 4; s++) {
        const int srcl = (lane & 7) * 4;
        uint32_t vb = __shfl_sync(0xffffffffu, Bp[s], srcl);
        uint32_t vs = __shfl_sync(0xffffffffu, Sp[s], srcl);
        if ((lane >> 3) == s) { myB = vb; myS = vs; }
    }

    // ---- tiered decision (1 int unit = 1/256 score) ----
    const int tok = blockIdx.x * TOK_CTA + tid;
    const uint32_t I1 = myB >> 9, I2 = myS >> 9;
    int best_k = 511 - (int)(myB & 511u);
    const float marg = smarg[tid];
    const int ithr = (int)(256.f * marg) + 3;
    bool fullf = (I1 < 512u) || (I1 >= 8388000u);

    // tier 2: exact fp32 pair rescore of {k1, k2}
    if (!fullf && (int)(I1 - I2) <= ithr) {
        const int k1 = best_k, k2 = 511 - (int)(myS & 511u);
        const float4* xp = reinterpret_cast<const float4*>(x + (size_t)tok * DIM);
        const float4* va = reinterpret_cast<const float4*>(vq + (size_t)k1 * DIM);
        const float4* vb = reinterpret_cast<const float4*>(vq + (size_t)k2 * DIM);
        float e1 = 0.f, e2 = 0.f;
        #pragma unroll
        for (int i = 0; i < 16; i++) {
            float4 xv = __ldg(xp + i), u = __ldg(va + i), w = __ldg(vb + i);
            e1 = fmaf(xv.x, u.x, fmaf(xv.y, u.y, fmaf(xv.z, u.z, fmaf(xv.w, u.w, e1))));
            e2 = fmaf(xv.x, w.x, fmaf(xv.y, w.y, fmaf(xv.z, w.z, fmaf(xv.w, w.w, e2))));
        }
        e1 -= sbias[k1];
        e2 -= sbias[k2];
        const float s2f = (float)I2 * 0.00390625f - 256.f;
        const float emax = fmaxf(e1, e2);
        const int km = (e2 > e1) ? k2 : ((e1 > e2) ? k1 : min(k1, k2));
        if (emax >= s2f + marg + 0.005f) best_k = km;
        else fullf = true;
    }

    // tier 3: cooperative exact full rescan (rare)
    {
        unsigned rm = __ballot_sync(0xffffffffu, fullf);
        const int sub = lane & 3;
        const int grp = lane >> 2;
        while (rm) {
            const int src = __ffs(rm) - 1;
            rm &= rm - 1;
            const int stok = blockIdx.x * TOK_CTA + wid * 32 + src;
            const float4* xp = reinterpret_cast<const float4*>(x + (size_t)stok * DIM) + sub * 4;
            float4 x0 = __ldg(xp), x1 = __ldg(xp + 1), x2 = __ldg(xp + 2), x3 = __ldg(xp + 3);
            float be = -3.4e38f;
            int bkk = 0;
            #pragma unroll 1
            for (int i = 0; i < 64; i++) {
                const int r = i * 8 + grp;
                const float4* vr = reinterpret_cast<const float4*>(vq + (size_t)r * DIM) + sub * 4;
                float4 v0 = __ldg(vr), v1 = __ldg(vr + 1), v2 = __ldg(vr + 2), v3 = __ldg(vr + 3);
                float d = x0.x * v0.x;
                d = fmaf(x0.y, v0.y, d); d = fmaf(x0.z, v0.z, d); d = fmaf(x0.w, v0.w, d);
                d = fmaf(x1.x, v1.x, d); d = fmaf(x1.y, v1.y, d); d = fmaf(x1.z, v1.z, d); d = fmaf(x1.w, v1.w, d);
                d = fmaf(x2.x, v2.x, d); d = fmaf(x2.y, v2.y, d); d = fmaf(x2.z, v2.z, d); d = fmaf(x2.w, v2.w, d);
                d = fmaf(x3.x, v3.x, d); d = fmaf(x3.y, v3.y, d); d = fmaf(x3.z, v3.z, d); d = fmaf(x3.w, v3.w, d);
                d += __shfl_xor_sync(0xffffffffu, d, 1);
                d += __shfl_xor_sync(0xffffffffu, d, 2);
                d -= sbias[r];
                if (d > be) { be = d; bkk = r; }
            }
            #pragma unroll
            for (int o = 4; o < 32; o <<= 1) {
                float ob = __shfl_xor_sync(0xffffffffu, be, o);
                int   ok = __shfl_xor_sync(0xffffffffu, bkk, o);
                if (ob > be || (ob == be && ok < bkk)) { be = ob; bkk = ok; }
            }
            if (lane == src) best_k = bkk;
        }
    }

    // ---- cooperative epilogue, batched (MLP 8): gather + vector-RED ----
    {
        const int cc = lane & 15;
        const int half = lane >> 4;
        #pragma unroll
        for (int p4 = 0; p4 < 4; p4++) {
            int kkv[4], gtv[4];
            float4 vv[4], xv[4];
            #pragma unroll
            for (int u = 0; u < 4; u++) {
                const int j = (p4 * 4 + u) * 2 + half;
                kkv[u] = __shfl_sync(0xffffffffu, best_k, j);
                gtv[u] = blockIdx.x * TOK_CTA + wid * 32 + j;
                vv[u] = __ldg(reinterpret_cast<const float4*>(vq + (size_t)kkv[u] * DIM) + cc);
                xv[u] = __ldg(reinterpret_cast<const float4*>(x + (size_t)gtv[u] * DIM) + cc);
            }
            #pragma unroll
            for (int u = 0; u < 4; u++) {
                reinterpret_cast<float4*>(q_out + (size_t)gtv[u] * DIM)[cc] = vv[u];
                red4(g_cs + (size_t)kkv[u] * DIM + cc * 4, xv[u]);
                if (cc == 0) atomicAdd(&g_cn[kkv[u]], 1.0f);
            }
        }
    }

    // ---- last CTA performs the EMA finalize ----
    __threadfence();
    __syncthreads();
    __shared__ int s_last;
    if (tid == 0) s_last = (atomicAdd(&g_done, 1u) == (unsigned)(gridDim.x - 1));
    __syncthreads();
    if (!s_last) return;
    __threadfence();

    float* scn = reinterpret_cast<float*>(smem);
    for (int k = tid; k < KCB; k += TPB) {
        float cn_acc = g_cn[k];
        g_cn[k] = 0.f;
        float cn_new = cn_in[k] * GAMMA + cn_acc * (1.0f - GAMMA);
        cn_out[k] = cn_new;
        scn[k] = cn_new;
    }
    __syncthreads();
    for (int idx = tid; idx < KCB * DIM; idx += TPB) {
        float cs_acc = g_cs[idx];
        g_cs[idx] = 0.f;
        float cs_new = cs_in[idx] * GAMMA + cs_acc * (1.0f - GAMMA);
        cs_out[idx] = cs_new;
        vq_out[idx] = cs_new / scn[idx >> 6];
    }
    if (tid == 0) g_done = 0u;
}

extern "C" void kernel_launch(void* const* d_in, const int* in_sizes, int n_in,
                              void* d_out, int out_size) {
    const float* x  = (const float*)d_in[0];   // [N, 64]
    const float* vq = (const float*)d_in[1];   // [512, 64]
    const float* cs = (const float*)d_in[2];   // [512, 64]
    const float* cn = (const float*)d_in[3];   // [512]

    float* out    = (float*)d_out;
    float* q_out  = out;                        // [N, 64]
    float* vq_out = out + (size_t)N_TOK * DIM;  // [512, 64]
    float* cs_out = vq_out + (size_t)KCB * DIM; // [512, 64]
    float* cn_out = cs_out + (size_t)KCB * DIM; // [512]

    cudaFuncSetAttribute(vq_kernel, cudaFuncAttributeMaxDynamicSharedMemorySize, SMEM_BYTES);
    init_kernel<<<16, 256>>>(vq);
    vq_kernel<<<NCTA, TPB, SMEM_BYTES>>>(x, vq, cs, cn, q_out, vq_out, cs_out, cn_out);
}